// round 1
// baseline (speedup 1.0000x reference)
#include <cuda_runtime.h>
#include <cuda_bf16.h>

#define N_NODES 50000
#define N_EDGES 800000
#define D 64

// Scratch (no allocations allowed): exp scores, softmax denominators, aggregated messages.
__device__ __align__(16) float g_exp_s[N_EDGES];
__device__ __align__(16) float g_denom[N_NODES];
__device__ __align__(16) float g_hsum[N_NODES * D];

// ---------------------------------------------------------------------------
// Zero the accumulators (d_out is re-poisoned each run; these are device globals
// that carry state across graph replays, so they must be re-zeroed every launch).
// ---------------------------------------------------------------------------
__global__ void kgcn_zero_kernel() {
    int i = blockIdx.x * blockDim.x + threadIdx.x;
    int stride = gridDim.x * blockDim.x;
    float4 z = make_float4(0.f, 0.f, 0.f, 0.f);
    float4* h4 = reinterpret_cast<float4*>(g_hsum);
    const int TOT_H4 = N_NODES * D / 4;
    for (int idx = i; idx < TOT_H4; idx += stride) h4[idx] = z;
    float4* d4 = reinterpret_cast<float4*>(g_denom);
    const int TOT_D4 = N_NODES / 4;   // 50000 divisible by 4
    for (int idx = i; idx < TOT_D4; idx += stride) d4[idx] = z;
}

// ---------------------------------------------------------------------------
// Kernel 1: per-edge score = exp(dot(h_src[src], e)); atomic denom per dst.
// Half-warp (16 lanes x float4) per edge = exactly one 256B row per group.
// ---------------------------------------------------------------------------
__global__ void kgcn_score_kernel(const float* __restrict__ h_src,
                                  const float* __restrict__ e,
                                  const int* __restrict__ src,
                                  const int* __restrict__ dst) {
    int tid  = blockIdx.x * blockDim.x + threadIdx.x;
    int edge = tid >> 4;
    int sub  = tid & 15;
    if (edge >= N_EDGES) return;   // never taken: E*16 == grid size exactly

    int s = src[edge];
    float4 hv = reinterpret_cast<const float4*>(h_src)[(size_t)s * 16 + sub];
    float4 ev = reinterpret_cast<const float4*>(e)[(size_t)edge * 16 + sub];

    float dot = hv.x * ev.x + hv.y * ev.y + hv.z * ev.z + hv.w * ev.w;
    // reduce within the 16-lane group
    dot += __shfl_xor_sync(0xffffffffu, dot, 1);
    dot += __shfl_xor_sync(0xffffffffu, dot, 2);
    dot += __shfl_xor_sync(0xffffffffu, dot, 4);
    dot += __shfl_xor_sync(0xffffffffu, dot, 8);

    if (sub == 0) {
        float ex = __expf(dot);
        g_exp_s[edge] = ex;
        atomicAdd(&g_denom[dst[edge]], ex);
    }
}

// ---------------------------------------------------------------------------
// Kernel 2: pi = exp_s / denom[dst];  h_sum[dst] += pi * h_src[src]
// Half-warp per edge; one red.global.add.v4.f32 per lane (16 per edge).
// ---------------------------------------------------------------------------
__global__ void kgcn_scatter_kernel(const float* __restrict__ h_src,
                                    const int* __restrict__ src,
                                    const int* __restrict__ dst) {
    int tid  = blockIdx.x * blockDim.x + threadIdx.x;
    int edge = tid >> 4;
    int sub  = tid & 15;
    if (edge >= N_EDGES) return;

    int s = src[edge];
    int d = dst[edge];
    float pi = g_exp_s[edge] / g_denom[d];

    float4 hv = reinterpret_cast<const float4*>(h_src)[(size_t)s * 16 + sub];
    float* addr = &g_hsum[(size_t)d * D + sub * 4];
    asm volatile("red.global.add.v4.f32 [%0], {%1, %2, %3, %4};"
                 :: "l"(addr),
                    "f"(hv.x * pi), "f"(hv.y * pi), "f"(hv.z * pi), "f"(hv.w * pi)
                 : "memory");
}

// ---------------------------------------------------------------------------
// Kernel 3: out[n] = W @ concat(h_dst[n], h_sum[n]) + b
// Warp per node. W (64x128) transposed into shared as W_s[k][j] so that each
// lane's float2 read of columns (2*lane, 2*lane+1) is conflict-free.
// h row (128 vals) lives in 4 regs/lane, broadcast via shfl.
// ---------------------------------------------------------------------------
__global__ void kgcn_out_kernel(const float* __restrict__ h_dst,
                                const float* __restrict__ W,
                                const float* __restrict__ b,
                                float* __restrict__ out) {
    __shared__ float W_s[128 * 64];
    for (int i = threadIdx.x; i < 64 * 128; i += blockDim.x) {
        int j = i >> 7;     // output index 0..63
        int k = i & 127;    // input index  0..127
        W_s[k * 64 + j] = W[i];
    }
    __syncthreads();

    int lane   = threadIdx.x & 31;
    int warp   = (blockIdx.x * blockDim.x + threadIdx.x) >> 5;
    int nwarps = (gridDim.x * blockDim.x) >> 5;

    float b0 = b[2 * lane];
    float b1 = b[2 * lane + 1];

    for (int node = warp; node < N_NODES; node += nwarps) {
        size_t base = (size_t)node * D;
        float h0 = h_dst[base + lane];
        float h1 = h_dst[base + 32 + lane];
        float h2 = g_hsum[base + lane];
        float h3 = g_hsum[base + 32 + lane];

        float acc0 = b0, acc1 = b1;
        #pragma unroll
        for (int k = 0; k < 128; k++) {
            float hv;
            if      (k < 32) hv = __shfl_sync(0xffffffffu, h0, k);
            else if (k < 64) hv = __shfl_sync(0xffffffffu, h1, k - 32);
            else if (k < 96) hv = __shfl_sync(0xffffffffu, h2, k - 64);
            else             hv = __shfl_sync(0xffffffffu, h3, k - 96);
            float2 w = *reinterpret_cast<const float2*>(&W_s[k * 64 + 2 * lane]);
            acc0 = fmaf(hv, w.x, acc0);
            acc1 = fmaf(hv, w.y, acc1);
        }
        reinterpret_cast<float2*>(out)[(size_t)node * 32 + lane] =
            make_float2(acc0, acc1);
    }
}

// ---------------------------------------------------------------------------
// Launch
// Inputs (metadata order): 0 h_src, 1 h_dst, 2 e, 3 src, 4 dst, 5 W, 6 b
// ---------------------------------------------------------------------------
extern "C" void kernel_launch(void* const* d_in, const int* in_sizes, int n_in,
                              void* d_out, int out_size) {
    const float* h_src = (const float*)d_in[0];
    const float* h_dst = (const float*)d_in[1];
    const float* e     = (const float*)d_in[2];
    const int*   src   = (const int*)d_in[3];
    const int*   dst   = (const int*)d_in[4];
    const float* W     = (const float*)d_in[5];
    const float* b     = (const float*)d_in[6];
    float* out = (float*)d_out;

    kgcn_zero_kernel<<<416, 256>>>();

    // 800000 edges * 16 threads/edge = 12,800,000 threads = 50000 blocks * 256
    kgcn_score_kernel<<<50000, 256>>>(h_src, e, src, dst);
    kgcn_scatter_kernel<<<50000, 256>>>(h_src, src, dst);

    // 888 blocks = 6 per SM; W loaded into smem once per block
    kgcn_out_kernel<<<888, 256>>>(h_dst, W, b, out);
}

// round 2
// speedup vs baseline: 1.3544x; 1.3544x over previous
#include <cuda_runtime.h>
#include <cuda_bf16.h>

#define N_NODES 50000
#define N_EDGES 800000
#define D 64

// Scratch (no allocations allowed): exp scores, softmax denominators, aggregated messages.
__device__ __align__(16) float g_exp_s[N_EDGES];
__device__ __align__(16) float g_denom[N_NODES];
__device__ __align__(16) float g_hsum[N_NODES * D];

// ---------------------------------------------------------------------------
// Zero the accumulators (device globals carry state across graph replays,
// so they must be re-zeroed every launch).
// ---------------------------------------------------------------------------
__global__ void kgcn_zero_kernel() {
    int i = blockIdx.x * blockDim.x + threadIdx.x;
    int stride = gridDim.x * blockDim.x;
    float4 z = make_float4(0.f, 0.f, 0.f, 0.f);
    float4* h4 = reinterpret_cast<float4*>(g_hsum);
    const int TOT_H4 = N_NODES * D / 4;
    for (int idx = i; idx < TOT_H4; idx += stride) h4[idx] = z;
    float4* d4 = reinterpret_cast<float4*>(g_denom);
    const int TOT_D4 = N_NODES / 4;   // 50000 divisible by 4
    for (int idx = i; idx < TOT_D4; idx += stride) d4[idx] = z;
}

// ---------------------------------------------------------------------------
// Kernel 1: per-edge score = exp(dot(h_src[src], e)); atomic denom per dst.
// Half-warp (16 lanes x float4) per edge = exactly one 256B row per group.
// ---------------------------------------------------------------------------
__global__ void kgcn_score_kernel(const float* __restrict__ h_src,
                                  const float* __restrict__ e,
                                  const int* __restrict__ src,
                                  const int* __restrict__ dst) {
    int tid  = blockIdx.x * blockDim.x + threadIdx.x;
    int edge = tid >> 4;
    int sub  = tid & 15;
    if (edge >= N_EDGES) return;   // never taken: E*16 == grid size exactly

    int s = src[edge];
    float4 hv = reinterpret_cast<const float4*>(h_src)[(size_t)s * 16 + sub];
    float4 ev = reinterpret_cast<const float4*>(e)[(size_t)edge * 16 + sub];

    float dot = hv.x * ev.x + hv.y * ev.y + hv.z * ev.z + hv.w * ev.w;
    dot += __shfl_xor_sync(0xffffffffu, dot, 1);
    dot += __shfl_xor_sync(0xffffffffu, dot, 2);
    dot += __shfl_xor_sync(0xffffffffu, dot, 4);
    dot += __shfl_xor_sync(0xffffffffu, dot, 8);

    if (sub == 0) {
        float ex = __expf(dot);
        g_exp_s[edge] = ex;
        atomicAdd(&g_denom[dst[edge]], ex);
    }
}

// ---------------------------------------------------------------------------
// Kernel 2: pi = exp_s / denom[dst];  h_sum[dst] += pi * h_src[src]
// Half-warp per edge; one red.global.add.v4.f32 per lane (16 per edge).
// ---------------------------------------------------------------------------
__global__ void kgcn_scatter_kernel(const float* __restrict__ h_src,
                                    const int* __restrict__ src,
                                    const int* __restrict__ dst) {
    int tid  = blockIdx.x * blockDim.x + threadIdx.x;
    int edge = tid >> 4;
    int sub  = tid & 15;
    if (edge >= N_EDGES) return;

    int s = src[edge];
    int d = dst[edge];
    float pi = g_exp_s[edge] / g_denom[d];

    float4 hv = reinterpret_cast<const float4*>(h_src)[(size_t)s * 16 + sub];
    float* addr = &g_hsum[(size_t)d * D + sub * 4];
    asm volatile("red.global.add.v4.f32 [%0], {%1, %2, %3, %4};"
                 :: "l"(addr),
                    "f"(hv.x * pi), "f"(hv.y * pi), "f"(hv.z * pi), "f"(hv.w * pi)
                 : "memory");
}

// ---------------------------------------------------------------------------
// Kernel 3: out = concat(h_dst, h_sum) @ W^T + b  — register-tiled SGEMM.
// Block: 256 threads -> 128-node x 64-col tile; thread: 8 nodes x 4 cols.
// k=128 processed in 4 chunks of 32 (chunks 0-1 = h_dst, 2-3 = g_hsum).
// Shared: W_s[k][j] 32KB + h_s[node][kk] 16KB = 48KB exactly.
// Inner loop: 1 LDS.128 + 8 scalar LDS per 32 FMAs -> FMA-bound.
// ---------------------------------------------------------------------------
__global__ void __launch_bounds__(256) kgcn_out_kernel(
        const float* __restrict__ h_dst,
        const float* __restrict__ W,
        const float* __restrict__ b,
        float* __restrict__ out) {
    __shared__ float W_s[128 * 64];   // [k][j], transposed from W[j][k]
    __shared__ float h_s[128 * 32];   // [local node][kk]

    const int tid = threadIdx.x;

    // Load W transposed: W is [64 out][128 in] row-major.
    for (int i = tid; i < 64 * 128; i += 256) {
        int j = i >> 7;     // out col 0..63
        int k = i & 127;    // in  idx 0..127
        W_s[k * 64 + j] = W[i];
    }

    const int tx = tid & 15;      // owns output cols 4*tx .. 4*tx+3
    const int ty = tid >> 4;      // owns local nodes 8*ty .. 8*ty+7
    const int node0 = blockIdx.x * 128;

    float acc[8][4];
    #pragma unroll
    for (int n = 0; n < 8; n++) {
        acc[n][0] = 0.f; acc[n][1] = 0.f; acc[n][2] = 0.f; acc[n][3] = 0.f;
    }

    #pragma unroll
    for (int c = 0; c < 4; c++) {
        const float* srcp = (c < 2) ? h_dst : g_hsum;
        const int kof4 = (c & 1) * 8;   // float4 offset within 64-float row

        __syncthreads();   // protect h_s from previous chunk's readers (covers W on c=0)
        // Stage 128 nodes x 32 floats (1024 float4, 4 per thread), coalesced.
        #pragma unroll
        for (int r = 0; r < 4; r++) {
            int idx = tid + r * 256;    // 0..1023
            int n   = idx >> 3;         // local node
            int q   = idx & 7;          // float4 slot within chunk row
            float4 v = make_float4(0.f, 0.f, 0.f, 0.f);
            int gn = node0 + n;
            if (gn < N_NODES)
                v = reinterpret_cast<const float4*>(srcp)[(size_t)gn * 16 + kof4 + q];
            int base = n * 32 + q * 4;
            h_s[base + 0] = v.x; h_s[base + 1] = v.y;
            h_s[base + 2] = v.z; h_s[base + 3] = v.w;
        }
        __syncthreads();

        const float* Wrow = &W_s[(c * 32) * 64 + 4 * tx];
        #pragma unroll 8
        for (int kk = 0; kk < 32; kk++) {
            float4 w = *reinterpret_cast<const float4*>(Wrow + kk * 64);
            #pragma unroll
            for (int n = 0; n < 8; n++) {
                float hv = h_s[(8 * ty + n) * 32 + kk];
                acc[n][0] = fmaf(hv, w.x, acc[n][0]);
                acc[n][1] = fmaf(hv, w.y, acc[n][1]);
                acc[n][2] = fmaf(hv, w.z, acc[n][2]);
                acc[n][3] = fmaf(hv, w.w, acc[n][3]);
            }
        }
    }

    float4 bb = *reinterpret_cast<const float4*>(&b[4 * tx]);
    #pragma unroll
    for (int n = 0; n < 8; n++) {
        int gn = node0 + 8 * ty + n;
        if (gn < N_NODES) {
            float4 o = make_float4(acc[n][0] + bb.x, acc[n][1] + bb.y,
                                   acc[n][2] + bb.z, acc[n][3] + bb.w);
            reinterpret_cast<float4*>(out)[(size_t)gn * 16 + tx] = o;
        }
    }
}

// ---------------------------------------------------------------------------
// Launch
// Inputs (metadata order): 0 h_src, 1 h_dst, 2 e, 3 src, 4 dst, 5 W, 6 b
// ---------------------------------------------------------------------------
extern "C" void kernel_launch(void* const* d_in, const int* in_sizes, int n_in,
                              void* d_out, int out_size) {
    const float* h_src = (const float*)d_in[0];
    const float* h_dst = (const float*)d_in[1];
    const float* e     = (const float*)d_in[2];
    const int*   src   = (const int*)d_in[3];
    const int*   dst   = (const int*)d_in[4];
    const float* W     = (const float*)d_in[5];
    const float* b     = (const float*)d_in[6];
    float* out = (float*)d_out;

    kgcn_zero_kernel<<<416, 256>>>();

    // 800000 edges * 16 threads/edge = 12,800,000 threads = 50000 blocks * 256
    kgcn_score_kernel<<<50000, 256>>>(h_src, e, src, dst);
    kgcn_scatter_kernel<<<50000, 256>>>(h_src, src, dst);

    // 391 blocks of 128 nodes
    kgcn_out_kernel<<<(N_NODES + 127) / 128, 256>>>(h_dst, W, b, out);
}